// round 13
// baseline (speedup 1.0000x reference)
#include <cuda_runtime.h>
#include <cuda_bf16.h>
#include <cuda_fp16.h>
#include <cstdint>

// ---------------------------------------------------------------------------
// DirectGCNLayer on GB300 (sm_103a) — R12
//
//   Wc_in  = W_main_in  + W_shared ;  Wc_out = W_main_out + W_shared
//   H      = X @ [Wc_in | Wc_out]              (N x 128, stored FP16)
//   out[t] = C_in[t] *(sum_in  w*H[src][0:64]   + bc_in)
//          + C_out[t]*(sum_out w*H[src][64:128] + bc_out)
//
// GEMM: mma.sync m16n8k16 bf16 (HMMA; harness ptxas target is plain sm_103,
// tcgen05 rejected), bf16 hi/lo split, 3 passes, fp32 accum.
// R12: (a) gather reads packed {src,w} u64 pairs (2 edges / LDG.128),
//      cutting LSU ops per edge 3 -> 1.5 (gather was LSU-issue bound);
//      (b) GEMM tile 64x128 -> 102KB smem -> 2 CTAs/SM overlap, cp.async B.
// ---------------------------------------------------------------------------

#define MAX_N 100000
#define MAX_E 1000000

typedef unsigned long long u64;
typedef unsigned int u32;

// padded bf16 tile row stride
#define TSTRIDE 272
#define BT_BYTES (128 * TSTRIDE)       // B tile: 128 n-rows  (34816 B)
#define AT_BYTES (64 * TSTRIDE)        // A tile:  64 m-rows  (17408 B)

__device__ __half g_H2[(size_t)MAX_N * 128];        // 25.6 MB, fp16 H
__device__ float g_bc[128];                         // combined biases [in|out]
__device__ int   g_off_in[MAX_N + 1];
__device__ int   g_off_out[MAX_N + 1];
__device__ __align__(16) u64 g_pk_in[MAX_E];        // {src, w} packed
__device__ __align__(16) u64 g_pk_out[MAX_E];
__device__ __align__(16) unsigned char g_Bhi[BT_BYTES]; // B=Wc^T bf16 hi, padded
__device__ __align__(16) unsigned char g_Blo[BT_BYTES]; // B=Wc^T bf16 lo, padded

// ---- helpers ---------------------------------------------------------------
__device__ __forceinline__ u32 smem_u32(const void* p) {
    u32 a; asm("{ .reg .u64 t; cvta.to.shared.u64 t, %1; cvt.u32.u64 %0, t; }"
               : "=r"(a) : "l"(p));
    return a;
}
#define LDSM_X4(r0, r1, r2, r3, addr) \
    asm volatile("ldmatrix.sync.aligned.m8n8.x4.shared.b16 {%0,%1,%2,%3}, [%4];" \
                 : "=r"(r0), "=r"(r1), "=r"(r2), "=r"(r3) : "r"(addr))
__device__ __forceinline__ void mma_bf16(float* c, const u32* a, u32 b0, u32 b1) {
    asm volatile(
        "mma.sync.aligned.m16n8k16.row.col.f32.bf16.bf16.f32 "
        "{%0,%1,%2,%3}, {%4,%5,%6,%7}, {%8,%9}, {%0,%1,%2,%3};"
        : "+f"(c[0]), "+f"(c[1]), "+f"(c[2]), "+f"(c[3])
        : "r"(a[0]), "r"(a[1]), "r"(a[2]), "r"(a[3]), "r"(b0), "r"(b1));
}
__device__ __forceinline__ void cp_async16(u32 dst, const void* src) {
    asm volatile("cp.async.cg.shared.global [%0], [%1], 16;" :: "r"(dst), "l"(src));
}

// ---------------------------------------------------------------------------
// prep: B[n][k] = Wc[k][n] (n<64: in-path, n>=64: out-path), split to bf16
// hi/lo, padded global images. Also combined biases.
// ---------------------------------------------------------------------------
__global__ void prep_kernel(const float* __restrict__ Wmi, const float* __restrict__ Wmo,
                            const float* __restrict__ Wsh,
                            const float* __restrict__ bmi, const float* __restrict__ bmo,
                            const float* __restrict__ bsi, const float* __restrict__ bso) {
    int i = blockIdx.x * blockDim.x + threadIdx.x;
    if (i < 128 * 128) {
        int n = i >> 7, k = i & 127;
        float w;
        if (n < 64) w = Wmi[k * 64 + n] + Wsh[k * 64 + n];
        else        w = Wmo[k * 64 + (n - 64)] + Wsh[k * 64 + (n - 64)];
        __nv_bfloat16 hb = __float2bfloat16(w);
        __nv_bfloat16 lb = __float2bfloat16(w - __bfloat162float(hb));
        int off = n * TSTRIDE + k * 2;
        *(__nv_bfloat16*)(g_Bhi + off) = hb;
        *(__nv_bfloat16*)(g_Blo + off) = lb;
    }
    if (i < 64) {
        g_bc[i]      = bmi[i] + bsi[i];
        g_bc[64 + i] = bmo[i] + bso[i];
    }
}

// ---------------------------------------------------------------------------
// edges: CSR offsets (off[t] = first e with tgt[e] >= t) AND {src,w} packing,
// both lists, one launch.
// ---------------------------------------------------------------------------
__global__ void edges_kernel(const int* __restrict__ si, const float* __restrict__ wi,
                             const int* __restrict__ ti, int Ein,
                             const int* __restrict__ so, const float* __restrict__ wo,
                             const int* __restrict__ to, int Eout, int N) {
    int e = blockIdx.x * blockDim.x + threadIdx.x;
    if (e < Ein)
        g_pk_in[e] = (u64)(u32)__ldg(&si[e]) | ((u64)__float_as_uint(__ldg(&wi[e])) << 32);
    if (e < Eout)
        g_pk_out[e] = (u64)(u32)__ldg(&so[e]) | ((u64)__float_as_uint(__ldg(&wo[e])) << 32);
    if (e <= Ein) {
        int cur  = (e < Ein) ? ti[e]     : N;
        int prev = (e > 0)   ? ti[e - 1] : -1;
        for (int t = prev + 1; t <= cur; ++t) g_off_in[t] = e;
    }
    if (e <= Eout) {
        int cur  = (e < Eout) ? to[e]     : N;
        int prev = (e > 0)    ? to[e - 1] : -1;
        for (int t = prev + 1; t <= cur; ++t) g_off_out[t] = e;
    }
}

// ---------------------------------------------------------------------------
// HMMA GEMM: 64 rows x 128 cols per CTA (2 CTAs/SM). 8 warps: wr=wid&1 (rows
// wr*32..+32), wc=wid>>1 (cols wc*32..+32). B copied via cp.async.
// SMEM: Ahi|Alo (17408 B each) then Bhi|Blo (34816 B each) = 104448 B.
// ---------------------------------------------------------------------------
#define SA_HI 0
#define SA_LO AT_BYTES
#define SB_HI (2 * AT_BYTES)
#define SB_LO (2 * AT_BYTES + BT_BYTES)
#define GEMM_SMEM (2 * AT_BYTES + 2 * BT_BYTES)   // 104448

__global__ __launch_bounds__(256, 2) void gemm_kernel(const float* __restrict__ X, int N) {
    extern __shared__ __align__(16) char smem[];
    u32 sb = smem_u32(smem);
    int tid = threadIdx.x;
    int wid = tid >> 5;
    int lane = tid & 31;
    int node0 = blockIdx.x * 64;

    // async copy of pre-split B images (overlaps with X convert below)
    {
        const char* bh = (const char*)g_Bhi;
        const char* bl = (const char*)g_Blo;
        #pragma unroll
        for (int i = tid; i < BT_BYTES / 16; i += 256) {
            cp_async16(sb + SB_HI + i * 16, bh + i * 16);
            cp_async16(sb + SB_LO + i * 16, bl + i * 16);
        }
        asm volatile("cp.async.commit_group;");
    }

    // load X rows (64), split to bf16 hi/lo, store padded. 4 threads per row.
    {
        int r = tid >> 2, q = tid & 3;
        int n = node0 + r;
        const float4* xrow = (const float4*)(X + (size_t)n * 128);
        char* ahp = smem + SA_HI + r * TSTRIDE;
        char* alp = smem + SA_LO + r * TSTRIDE;
        #pragma unroll
        for (int kk = 0; kk < 8; ++kk) {
            int k4 = q * 8 + kk;              // float4 index; k = 4*k4
            float4 v = (n < N) ? __ldg(&xrow[k4]) : make_float4(0.f, 0.f, 0.f, 0.f);
            __nv_bfloat16 h0 = __float2bfloat16(v.x);
            __nv_bfloat16 h1 = __float2bfloat16(v.y);
            __nv_bfloat16 h2 = __float2bfloat16(v.z);
            __nv_bfloat16 h3 = __float2bfloat16(v.w);
            u32 hw0 = (u32)__bfloat16_as_ushort(h0) | ((u32)__bfloat16_as_ushort(h1) << 16);
            u32 hw1 = (u32)__bfloat16_as_ushort(h2) | ((u32)__bfloat16_as_ushort(h3) << 16);
            __nv_bfloat16 l0 = __float2bfloat16(v.x - __bfloat162float(h0));
            __nv_bfloat16 l1 = __float2bfloat16(v.y - __bfloat162float(h1));
            __nv_bfloat16 l2 = __float2bfloat16(v.z - __bfloat162float(h2));
            __nv_bfloat16 l3 = __float2bfloat16(v.w - __bfloat162float(h3));
            u32 lw0 = (u32)__bfloat16_as_ushort(l0) | ((u32)__bfloat16_as_ushort(l1) << 16);
            u32 lw1 = (u32)__bfloat16_as_ushort(l2) | ((u32)__bfloat16_as_ushort(l3) << 16);
            *(u64*)(ahp + k4 * 8) = (u64)hw0 | ((u64)hw1 << 32);
            *(u64*)(alp + k4 * 8) = (u64)lw0 | ((u64)lw1 << 32);
        }
    }
    asm volatile("cp.async.wait_group 0;" ::: "memory");
    __syncthreads();

    int wr = wid & 1;      // row group: rows wr*32..+31
    int wc = wid >> 1;     // col group: cols wc*32..+31

    u32 aHi[2], aLo[2];
    #pragma unroll
    for (int mt = 0; mt < 2; ++mt) {
        int row = wr * 32 + mt * 16 + (lane & 15);
        int kb = 16 * (lane >> 4);
        aHi[mt] = sb + SA_HI + row * TSTRIDE + kb;
        aLo[mt] = sb + SA_LO + row * TSTRIDE + kb;
    }
    u32 bHi[2], bLo[2];
    #pragma unroll
    for (int p = 0; p < 2; ++p) {
        int nrow = wc * 32 + p * 16 + ((lane >> 4) << 3) + (lane & 7);
        int kb = 16 * ((lane >> 3) & 1);
        bHi[p] = sb + SB_HI + nrow * TSTRIDE + kb;
        bLo[p] = sb + SB_LO + nrow * TSTRIDE + kb;
    }

    float c[2][4][4];
    #pragma unroll
    for (int mt = 0; mt < 2; ++mt)
        #pragma unroll
        for (int nt = 0; nt < 4; ++nt)
            #pragma unroll
            for (int q = 0; q < 4; ++q) c[mt][nt][q] = 0.f;

    #pragma unroll
    for (int ks = 0; ks < 8; ++ks) {
        int kb = ks * 32;
        u32 ah[2][4], al[2][4];
        #pragma unroll
        for (int mt = 0; mt < 2; ++mt) {
            LDSM_X4(ah[mt][0], ah[mt][1], ah[mt][2], ah[mt][3], aHi[mt] + kb);
            LDSM_X4(al[mt][0], al[mt][1], al[mt][2], al[mt][3], aLo[mt] + kb);
        }
        u32 bh[2][4], bl[2][4];
        #pragma unroll
        for (int p = 0; p < 2; ++p) {
            LDSM_X4(bh[p][0], bh[p][1], bh[p][2], bh[p][3], bHi[p] + kb);
            LDSM_X4(bl[p][0], bl[p][1], bl[p][2], bl[p][3], bLo[p] + kb);
        }
        #pragma unroll
        for (int mt = 0; mt < 2; ++mt)
            #pragma unroll
            for (int p = 0; p < 2; ++p) {
                mma_bf16(c[mt][2 * p],     ah[mt], bh[p][0], bh[p][1]);
                mma_bf16(c[mt][2 * p + 1], ah[mt], bh[p][2], bh[p][3]);
                mma_bf16(c[mt][2 * p],     ah[mt], bl[p][0], bl[p][1]);
                mma_bf16(c[mt][2 * p + 1], ah[mt], bl[p][2], bl[p][3]);
                mma_bf16(c[mt][2 * p],     al[mt], bh[p][0], bh[p][1]);
                mma_bf16(c[mt][2 * p + 1], al[mt], bh[p][2], bh[p][3]);
            }
    }

    // epilogue: d0,d1 -> row lane/4, cols (lane%4)*2; d2,d3 -> row +8.
    #pragma unroll
    for (int mt = 0; mt < 2; ++mt) {
        int row0 = node0 + wr * 32 + mt * 16 + (lane >> 2);
        #pragma unroll
        for (int hf = 0; hf < 2; ++hf) {
            int row = row0 + hf * 8;
            if (row < N) {
                u32* Hp = (u32*)g_H2 + (size_t)row * 64 + wc * 16 + (lane & 3);
                #pragma unroll
                for (int nt = 0; nt < 4; ++nt) {
                    __half2 v = __float22half2_rn(
                        make_float2(c[mt][nt][hf * 2], c[mt][nt][hf * 2 + 1]));
                    Hp[nt * 4] = *(u32*)&v;
                }
            }
        }
    }
}

// ---------------------------------------------------------------------------
// Pull gather: ONE WARP per target node. Lane l owns channel pair (2l, 2l+1).
// Packed edges: LDG.128 = 2 edges. H fp16: LDG.32/lane. fp32 accum.
// ---------------------------------------------------------------------------
__global__ __launch_bounds__(256) void gather_kernel(
        const float* __restrict__ Cin, const float* __restrict__ Cout,
        float* __restrict__ out, int N) {
    int gid = blockIdx.x * blockDim.x + threadIdx.x;
    int t = gid >> 5;
    if (t >= N) return;
    int l = gid & 31;                  // u32 index within row half; chans (2l,2l+1)

    float ax = 0.f, ay = 0.f, ox = 0.f, oy = 0.f;

    #pragma unroll
    for (int path = 0; path < 2; ++path) {
        int lo = path ? g_off_out[t] : g_off_in[t];
        int hi = path ? g_off_out[t + 1] : g_off_in[t + 1];
        const u64* Pk = path ? g_pk_out : g_pk_in;
        const u32* Hp = (const u32*)g_H2 + (path ? 32 + l : l);
        float sx = 0.f, sy = 0.f;
        int e = lo;
        if ((e < hi) && (e & 1)) {                 // align to even index
            u64 p = __ldg(&Pk[e]);
            int s = (int)(u32)p; float f = __uint_as_float((u32)(p >> 32));
            u32 h = __ldg(&Hp[s * 64]);
            float2 v = __half22float2(*(const __half2*)&h);
            sx += f * v.x; sy += f * v.y;
            ++e;
        }
        const ulonglong2* P2 = (const ulonglong2*)Pk;
        for (; e + 3 < hi; e += 4) {
            ulonglong2 pa = __ldg(&P2[e >> 1]);
            ulonglong2 pb = __ldg(&P2[(e >> 1) + 1]);
            int   s0 = (int)(u32)pa.x, s1 = (int)(u32)pa.y;
            int   s2 = (int)(u32)pb.x, s3 = (int)(u32)pb.y;
            float f0 = __uint_as_float((u32)(pa.x >> 32));
            float f1 = __uint_as_float((u32)(pa.y >> 32));
            float f2 = __uint_as_float((u32)(pb.x >> 32));
            float f3 = __uint_as_float((u32)(pb.y >> 32));
            u32 h0 = __ldg(&Hp[s0 * 64]);
            u32 h1 = __ldg(&Hp[s1 * 64]);
            u32 h2 = __ldg(&Hp[s2 * 64]);
            u32 h3 = __ldg(&Hp[s3 * 64]);
            float2 v0 = __half22float2(*(const __half2*)&h0);
            float2 v1 = __half22float2(*(const __half2*)&h1);
            float2 v2 = __half22float2(*(const __half2*)&h2);
            float2 v3 = __half22float2(*(const __half2*)&h3);
            sx += f0 * v0.x; sy += f0 * v0.y;
            sx += f1 * v1.x; sy += f1 * v1.y;
            sx += f2 * v2.x; sy += f2 * v2.y;
            sx += f3 * v3.x; sy += f3 * v3.y;
        }
        if (e + 1 < hi) {                          // even pair
            ulonglong2 pa = __ldg(&P2[e >> 1]);
            int   s0 = (int)(u32)pa.x, s1 = (int)(u32)pa.y;
            float f0 = __uint_as_float((u32)(pa.x >> 32));
            float f1 = __uint_as_float((u32)(pa.y >> 32));
            u32 h0 = __ldg(&Hp[s0 * 64]);
            u32 h1 = __ldg(&Hp[s1 * 64]);
            float2 v0 = __half22float2(*(const __half2*)&h0);
            float2 v1 = __half22float2(*(const __half2*)&h1);
            sx += f0 * v0.x; sy += f0 * v0.y;
            sx += f1 * v1.x; sy += f1 * v1.y;
            e += 2;
        }
        if (e < hi) {
            u64 p = __ldg(&Pk[e]);
            int s = (int)(u32)p; float f = __uint_as_float((u32)(p >> 32));
            u32 h = __ldg(&Hp[s * 64]);
            float2 v = __half22float2(*(const __half2*)&h);
            sx += f * v.x; sy += f * v.y;
        }
        if (path) { ox = sx; oy = sy; } else { ax = sx; ay = sy; }
    }

    int l2 = l * 2;
    float ci = __ldg(&Cin[t]), co = __ldg(&Cout[t]);
    float2 r;
    r.x = ci * (ax + g_bc[l2])     + co * (ox + g_bc[64 + l2]);
    r.y = ci * (ay + g_bc[l2 + 1]) + co * (oy + g_bc[65 + l2]);
    *(float2*)&out[(size_t)t * 64 + l2] = r;
}

// ---------------------------------------------------------------------------
extern "C" void kernel_launch(void* const* d_in, const int* in_sizes, int n_in,
                              void* d_out, int out_size) {
    const float* x    = (const float*)d_in[0];
    const float* Wmi  = (const float*)d_in[1];
    const float* Wmo  = (const float*)d_in[2];
    const float* Wsh  = (const float*)d_in[3];
    const float* bmi  = (const float*)d_in[4];
    const float* bmo  = (const float*)d_in[5];
    const float* bsi  = (const float*)d_in[6];
    const float* bso  = (const float*)d_in[7];
    const float* Cin  = (const float*)d_in[8];
    const float* Cout = (const float*)d_in[9];
    const int*   ei_in  = (const int*)d_in[10];
    const float* ew_in  = (const float*)d_in[11];
    const int*   ei_out = (const int*)d_in[12];
    const float* ew_out = (const float*)d_in[13];

    int N    = in_sizes[0] / 128;
    int Ein  = in_sizes[10] / 2;
    int Eout = in_sizes[12] / 2;
    float* out = (float*)d_out;

    int Emax = (Ein > Eout ? Ein : Eout);

    cudaFuncSetAttribute(gemm_kernel, cudaFuncAttributeMaxDynamicSharedMemorySize,
                         GEMM_SMEM);

    prep_kernel<<<64, 256>>>(Wmi, Wmo, Wsh, bmi, bmo, bsi, bso);
    edges_kernel<<<(Emax + 1 + 255) / 256, 256>>>(
        ei_in, ew_in, ei_in + Ein, Ein,
        ei_out, ew_out, ei_out + Eout, Eout, N);
    gemm_kernel<<<(N + 63) / 64, 256, GEMM_SMEM>>>(x, N);
    gather_kernel<<<((size_t)N * 32 + 255) / 256, 256>>>(Cin, Cout, out, N);
}